// round 9
// baseline (speedup 1.0000x reference)
#include <cuda_runtime.h>
#include <math.h>

#define T_ 100
#define B_ 64
#define I_ 256
#define H_ 512
#define G4_ (4*H_)   // 2048
#define H3_ (3*H_)   // 1536
#define BH_ (B_*H_)  // 32768
#define NBLK_ 128    // persistent blocks (<=148 SMs, all wave-1 resident)

typedef unsigned long long u64;

// ---------------- scratch (device globals) -----------------------------------
__device__ float g_xproj[(size_t)T_*B_*G4_];   // [T*B][4H] input-path gates + biases
__device__ float g_hseq[(size_t)(T_+1)*BH_];   // hseq[t] = h_{t-1} (for ev_hh GEMM)
__device__ u64   g_hT[2][(size_t)H_*B_/2];     // double-buffered transposed h [512][64]
__device__ float g_f[(size_t)T_*BH_];          // forget gates
__device__ float g_d[(size_t)T_*B_*H3_];       // d_i|d_f|d_g; suffix-scaled in place
__device__ unsigned g_arrive;                  // grid-barrier monotonic arrival counter

// ---------------- helpers -----------------------------------------------------
__device__ __forceinline__ u64 pack2(float x, float y) {
    u64 r; asm("mov.b64 %0, {%1,%2};" : "=l"(r) : "f"(x), "f"(y)); return r;
}
__device__ __forceinline__ void unpack2(u64 v, float& x, float& y) {
    asm("mov.b64 {%0,%1}, %2;" : "=f"(x), "=f"(y) : "l"(v));
}
__device__ __forceinline__ u64 fma2(u64 a, u64 b, u64 c) {
    u64 d; asm("fma.rn.f32x2 %0, %1, %2, %3;" : "=l"(d) : "l"(a), "l"(b), "l"(c)); return d;
}
__device__ __forceinline__ u64 ldcg64(const u64* p) {
    u64 v; asm volatile("ld.global.cg.b64 %0, [%1];" : "=l"(v) : "l"(p)); return v;
}
__device__ __forceinline__ unsigned ldacq32(const unsigned* p) {
    unsigned v; asm volatile("ld.acquire.gpu.global.u32 %0, [%1];" : "=r"(v) : "l"(p)); return v;
}

// ---------------- init --------------------------------------------------------
__global__ void k_init(const float* __restrict__ h0) {
    int i = blockIdx.x*256 + threadIdx.x;
    if (i < BH_) {
        g_hseq[i] = h0[i];
        int b = i >> 9, k = i & 511;
        ((float*)g_hT[0])[k*B_ + b] = h0[i];
    }
    if (i == 0) g_arrive = 0u;
}

// ---------------- K1: xproj = X @ Wih^T + b_ih + b_hh (f32x2) -----------------
__global__ __launch_bounds__(256, 2) void k1_xproj(
    const float* __restrict__ X, const float* __restrict__ W,
    const float* __restrict__ bih, const float* __restrict__ bhh)
{
    __shared__ __align__(16) float As[8][132];
    __shared__ __align__(16) float Ws[8][132];
    int m0 = blockIdx.y * 128;
    int n0 = blockIdx.x * 128;
    int tid = threadIdx.x;
    int lc = tid % 8;
    int lr = tid / 8;
    int ty = tid / 16, tx = tid % 16;

    u64 acc2[8][4];
    #pragma unroll
    for (int i=0;i<8;i++)
        #pragma unroll
        for (int j=0;j<4;j++) acc2[i][j]=0ull;

    for (int k0 = 0; k0 < I_; k0 += 8) {
        #pragma unroll
        for (int p = 0; p < 4; p++) {
            int r = lr + p*32;
            As[lc][r] = X[(size_t)(m0 + r)*I_ + k0 + lc];
            Ws[lc][r] = W[(size_t)(n0 + r)*I_ + k0 + lc];
        }
        __syncthreads();
        #pragma unroll
        for (int kk = 0; kk < 8; kk++) {
            float4 a0 = *(const float4*)&As[kk][ty*4];
            float4 a1 = *(const float4*)&As[kk][64 + ty*4];
            ulonglong2 bv0 = *(const ulonglong2*)&Ws[kk][tx*4];
            ulonglong2 bv1 = *(const ulonglong2*)&Ws[kk][64 + tx*4];
            u64 bb[4] = {bv0.x, bv0.y, bv1.x, bv1.y};
            float a[8] = {a0.x,a0.y,a0.z,a0.w,a1.x,a1.y,a1.z,a1.w};
            #pragma unroll
            for (int i=0;i<8;i++) {
                u64 ad = pack2(a[i], a[i]);
                #pragma unroll
                for (int j=0;j<4;j++) acc2[i][j] = fma2(ad, bb[j], acc2[i][j]);
            }
        }
        __syncthreads();
    }
    float bias[8];
    #pragma unroll
    for (int j=0;j<8;j++) {
        int n = n0 + ((j<4)? tx*4 + j : 64 + tx*4 + (j-4));
        bias[j] = bih[n] + bhh[n];
    }
    #pragma unroll
    for (int i=0;i<8;i++) {
        int m = m0 + ((i<4)? ty*4+i : 64+ty*4+(i-4));
        float* row = g_xproj + (size_t)m*G4_ + n0;
        float c[8];
        unpack2(acc2[i][0], c[0], c[1]);
        unpack2(acc2[i][1], c[2], c[3]);
        unpack2(acc2[i][2], c[4], c[5]);
        unpack2(acc2[i][3], c[6], c[7]);
        float4 v0 = make_float4(c[0]+bias[0], c[1]+bias[1], c[2]+bias[2], c[3]+bias[3]);
        float4 v1 = make_float4(c[4]+bias[4], c[5]+bias[5], c[6]+bias[6], c[7]+bias[7]);
        *(float4*)&row[tx*4]      = v0;
        *(float4*)&row[64+tx*4]   = v1;
    }
}

// ---------------- persistent recurrence kernel --------------------------------
// 128 blocks x 256 thr. Block owns h-cols hg = bid*4..bid*4+3 (16 gate cols).
// Dyn smem: Wd dup pairs [512][16] u64 (64KB) + exch 2048 floats (8KB) = 72KB.
__global__ __launch_bounds__(256, 1) void k_rec(
    const float* __restrict__ Whh, const float* __restrict__ c0,
    float* __restrict__ out_h, float* __restrict__ out_cx)
{
    extern __shared__ u64 dsm[];
    u64*   Wd   = dsm;                     // Wd[k*16 + q*4 + hl] = {w,w}
    float* exch = (float*)(dsm + 512*16);  // [kh][q][b][hl]

    int bid = blockIdx.x;
    int tid = threadIdx.x;

    {   // fill duplicated W slice
        int l  = tid & 15;
        int k0 = tid >> 4;           // 0..15
        int n  = (l>>2)*H_ + bid*4 + (l&3);
        for (int k = k0; k < H_; k += 16) {
            float w = Whh[(size_t)n*H_ + k];
            Wd[k*16 + l] = pack2(w, w);
        }
    }

    // pointwise cell ownership
    int pb  = tid >> 2;
    int phl = tid & 3;
    int hg  = bid*4 + phl;
    float c = c0[pb*H_ + hg];
    const float* xpbase = g_xproj + (size_t)pb*G4_;

    // GEMM warp mapping
    int w      = tid >> 5;
    int lane   = tid & 31;
    int bq     = w & 3;
    int khalf  = w >> 2;
    int bp     = lane >> 2;          // 0..7
    int q      = lane & 3;           // gate
    int b0     = bq*16 + bp*2;
    int hidx   = b0 >> 1;            // u64 index into hT row
    int kbase  = khalf * 256;

    __syncthreads();

    for (int t = 0; t < T_; ++t) {
        // ---- hoisted xproj loads (read-only; hide latency under GEMM) ----
        const float* xp = xpbase + (size_t)t*B_*G4_;
        float xpi = xp[hg];
        float xpf = xp[H_+hg];
        float xpg = xp[2*H_+hg];
        float xpo = xp[3*H_+hg];

        // ---- GEMM over this warp's k-half (f32x2, dup-W, prefetch dist 2) ----
        const u64* hp = g_hT[t & 1];
        u64 a0=0ull, a1=0ull, a2=0ull, a3=0ull;   // {b0,b0+1} for hl 0..3 at gate q
        u64 hA[8], hB[8];
        #pragma unroll
        for (int j=0;j<8;j++) hA[j] = ldcg64(&hp[(size_t)(kbase+j)*32 + hidx]);
        #pragma unroll
        for (int j=0;j<8;j++) hB[j] = ldcg64(&hp[(size_t)(kbase+8+j)*32 + hidx]);

        for (int kc = 0; kc < 256; kc += 16) {
            u64 cA[8];
            #pragma unroll
            for (int j=0;j<8;j++) cA[j] = hA[j];
            if (kc + 16 < 256) {
                #pragma unroll
                for (int j=0;j<8;j++)
                    hA[j] = ldcg64(&hp[(size_t)(kbase+kc+16+j)*32 + hidx]);
            }
            #pragma unroll
            for (int j=0;j<8;j++) {
                const u64* wrow = &Wd[(kbase+kc+j)*16 + q*4];
                ulonglong2 w01 = *(const ulonglong2*)&wrow[0];
                ulonglong2 w23 = *(const ulonglong2*)&wrow[2];
                a0 = fma2(cA[j], w01.x, a0);
                a1 = fma2(cA[j], w01.y, a1);
                a2 = fma2(cA[j], w23.x, a2);
                a3 = fma2(cA[j], w23.y, a3);
            }
            u64 cB[8];
            #pragma unroll
            for (int j=0;j<8;j++) cB[j] = hB[j];
            if (kc + 24 < 256) {
                #pragma unroll
                for (int j=0;j<8;j++)
                    hB[j] = ldcg64(&hp[(size_t)(kbase+kc+24+j)*32 + hidx]);
            }
            #pragma unroll
            for (int j=0;j<8;j++) {
                const u64* wrow = &Wd[(kbase+kc+8+j)*16 + q*4];
                ulonglong2 w01 = *(const ulonglong2*)&wrow[0];
                ulonglong2 w23 = *(const ulonglong2*)&wrow[2];
                a0 = fma2(cB[j], w01.x, a0);
                a1 = fma2(cB[j], w01.y, a1);
                a2 = fma2(cB[j], w23.x, a2);
                a3 = fma2(cB[j], w23.y, a3);
            }
        }
        // ---- exchange: exch[kh][q][b][hl]; a_i = {val(b0,hl=i), val(b0+1,hl=i)} ----
        {
            int base = ((khalf*4 + q)*64 + b0)*4;
            float lo, hi;
            unpack2(a0, lo, hi); exch[base+0] = lo; exch[base+4+0] = hi;
            unpack2(a1, lo, hi); exch[base+1] = lo; exch[base+4+1] = hi;
            unpack2(a2, lo, hi); exch[base+2] = lo; exch[base+4+2] = hi;
            unpack2(a3, lo, hi); exch[base+3] = lo; exch[base+4+3] = hi;
        }
        __syncthreads();

        // ---- pointwise for cell (pb, hg); h writes go to write buffer ----
        {
            float ai = xpi + exch[((0*4+0)*64+pb)*4+phl] + exch[((1*4+0)*64+pb)*4+phl];
            float af = xpf + exch[((0*4+1)*64+pb)*4+phl] + exch[((1*4+1)*64+pb)*4+phl];
            float ag = xpg + exch[((0*4+2)*64+pb)*4+phl] + exch[((1*4+2)*64+pb)*4+phl];
            float ao = xpo + exch[((0*4+3)*64+pb)*4+phl] + exch[((1*4+3)*64+pb)*4+phl];

            float ig = 1.f/(1.f+__expf(-ai));
            float fg = 1.f/(1.f+__expf(-af));
            float gg = tanhf(ag);
            float og = 1.f/(1.f+__expf(-ao));
            float cprev = c;
            float cy = fg*cprev + ig*gg;
            float hy = og*tanhf(cy);
            c = cy;

            size_t oidx = (size_t)t*BH_ + pb*H_ + hg;
            out_h[oidx] = hy;
            g_hseq[(size_t)(t+1)*BH_ + pb*H_ + hg] = hy;
            ((float*)g_hT[(t+1) & 1])[hg*B_ + pb] = hy;   // write buffer
            g_f[oidx] = fg;
            float* dp = g_d + ((size_t)t*B_ + pb)*H3_;
            dp[hg]        = gg*ig*(1.f-ig);
            dp[H_+hg]     = cprev*fg*(1.f-fg);
            dp[2*H_+hg]   = ig*(1.f-gg*gg);
            if (t == T_-1) out_cx[pb*H_ + hg] = cy;
        }

        // ---- grid barrier (release: fence+arrive; acquire: spin+sync) ----
        __threadfence();
        __syncthreads();
        if (tid == 0) {
            atomicAdd(&g_arrive, 1u);
            unsigned target = (unsigned)(NBLK_ * (t+1));
            while (ldacq32(&g_arrive) < target) { }
        }
        __syncthreads();
    }
}

// ---------------- K3: suffix forget-product scan (prefetch dist 2); ev_b ------
__global__ void k3_suffix(float* __restrict__ out_evb)
{
    int idx = blockIdx.x*256 + threadIdx.x;   // < BH_
    int b = idx >> 9;
    int h = idx & 511;
    float p = 1.f, s0 = 0.f, s1 = 0.f, s2 = 0.f;

    // prefetch t = T-1 and t = T-2
    float di0, df0, dg0, fv0, di1, df1, dg1, fv1;
    {
        const float* dp = g_d + ((size_t)(T_-1)*B_ + b)*H3_;
        di0 = dp[h]; df0 = dp[H_+h]; dg0 = dp[2*H_+h];
        fv0 = g_f[(size_t)(T_-1)*BH_ + idx];
        const float* dq = g_d + ((size_t)(T_-2)*B_ + b)*H3_;
        di1 = dq[h]; df1 = dq[H_+h]; dg1 = dq[2*H_+h];
        fv1 = g_f[(size_t)(T_-2)*BH_ + idx];
    }

    for (int t = T_-1; t >= 0; --t) {
        float cdi = di0, cdf = df0, cdg = dg0, cf = fv0;
        di0 = di1; df0 = df1; dg0 = dg1; fv0 = fv1;
        if (t >= 2) {
            const float* dn = g_d + ((size_t)(t-2)*B_ + b)*H3_;
            di1 = dn[h]; df1 = dn[H_+h]; dg1 = dn[2*H_+h];
            fv1 = g_f[(size_t)(t-2)*BH_ + idx];
        }
        float* dpc = g_d + ((size_t)t*B_ + b)*H3_;
        float wi = cdi*p, wf = cdf*p, wg = cdg*p;
        dpc[h] = wi; dpc[H_+h] = wf; dpc[2*H_+h] = wg;
        s0 += wi; s1 += wf; s2 += wg;
        p *= cf;
    }
    out_evb[(size_t)b*H3_ + h]        = s0;
    out_evb[(size_t)b*H3_ + H_ + h]   = s1;
    out_evb[(size_t)b*H3_ + 2*H_ + h] = s2;
}

// ---------------- K4/K5: batched ev GEMM (f32x2) ------------------------------
__global__ __launch_bounds__(256, 2) void k_ev(
    const float* __restrict__ Xin, float* __restrict__ C, int Idim)
{
    __shared__ __align__(16) float As[8][132];
    __shared__ __align__(16) float Xs[8][132];
    const float* X = Xin ? Xin : (const float*)g_hseq;
    int i0 = blockIdx.x*128;
    int j0 = blockIdx.y*128;
    int b  = blockIdx.z;
    int tid = threadIdx.x;
    int ty = tid/16, tx = tid%16;
    int lk = tid >> 5;
    int lj = (tid & 31) * 4;

    u64 acc2[8][4];
    #pragma unroll
    for (int i=0;i<8;i++)
        #pragma unroll
        for (int j=0;j<4;j++) acc2[i][j]=0ull;

    for (int t0 = 0; t0 < T_; t0 += 8) {
        int t = t0 + lk;
        if (t < T_) {
            *(float4*)&As[lk][lj] = *(const float4*)&g_d[((size_t)t*B_+b)*H3_ + j0 + lj];
            *(float4*)&Xs[lk][lj] = *(const float4*)&X[((size_t)t*B_+b)*Idim + i0 + lj];
        } else {
            float4 z = make_float4(0.f,0.f,0.f,0.f);
            *(float4*)&As[lk][lj] = z;
            *(float4*)&Xs[lk][lj] = z;
        }
        __syncthreads();
        #pragma unroll
        for (int kk=0;kk<8;kk++) {
            float4 a0 = *(const float4*)&As[kk][ty*4];
            float4 a1 = *(const float4*)&As[kk][64+ty*4];
            ulonglong2 xv0 = *(const ulonglong2*)&Xs[kk][tx*4];
            ulonglong2 xv1 = *(const ulonglong2*)&Xs[kk][64+tx*4];
            u64 xx[4] = {xv0.x, xv0.y, xv1.x, xv1.y};
            float a[8] = {a0.x,a0.y,a0.z,a0.w,a1.x,a1.y,a1.z,a1.w};
            #pragma unroll
            for (int i=0;i<8;i++) {
                u64 ad = pack2(a[i], a[i]);
                #pragma unroll
                for (int j=0;j<4;j++) acc2[i][j] = fma2(ad, xx[j], acc2[i][j]);
            }
        }
        __syncthreads();
    }
    #pragma unroll
    for (int i=0;i<8;i++) {
        int j = j0 + ((i<4)? ty*4+i : 64+ty*4+(i-4));
        float* row = C + (size_t)b*H3_*Idim + (size_t)j*Idim + i0;
        float cr[8];
        unpack2(acc2[i][0], cr[0], cr[1]);
        unpack2(acc2[i][1], cr[2], cr[3]);
        unpack2(acc2[i][2], cr[4], cr[5]);
        unpack2(acc2[i][3], cr[6], cr[7]);
        *(float4*)&row[tx*4]    = make_float4(cr[0],cr[1],cr[2],cr[3]);
        *(float4*)&row[64+tx*4] = make_float4(cr[4],cr[5],cr[6],cr[7]);
    }
}

// ---------------- launch -------------------------------------------------------
extern "C" void kernel_launch(void* const* d_in, const int* in_sizes, int n_in,
                              void* d_out, int out_size)
{
    const float* input = (const float*)d_in[0];
    const float* h0    = (const float*)d_in[1];
    const float* c0    = (const float*)d_in[2];
    const float* Wih   = (const float*)d_in[3];
    const float* Whh   = (const float*)d_in[4];
    const float* bih   = (const float*)d_in[5];
    const float* bhh   = (const float*)d_in[6];

    float* out      = (float*)d_out;
    float* out_h    = out;
    float* out_cx   = out_h  + (size_t)T_*BH_;
    float* out_evih = out_cx + BH_;
    float* out_evhh = out_evih + (size_t)B_*H3_*I_;
    float* out_evb  = out_evhh + (size_t)B_*H3_*H_;

    const int dyn_smem = 512*16*8 + 2048*4;   // 64KB Wd + 8KB exch = 73728
    cudaFuncSetAttribute(k_rec, cudaFuncAttributeMaxDynamicSharedMemorySize, dyn_smem);

    k_init<<<128,256>>>(h0);
    k1_xproj<<<dim3(16,50),256>>>(input, Wih, bih, bhh);
    k_rec<<<NBLK_, 256, dyn_smem>>>(Whh, c0, out_h, out_cx);
    k3_suffix<<<128,256>>>(out_evb);
    k_ev<<<dim3(I_/128, H3_/128, B_),256>>>(input, out_evih, I_);
    k_ev<<<dim3(H_/128, H3_/128, B_),256>>>(nullptr, out_evhh, H_);
}

// round 12
// speedup vs baseline: 1.2273x; 1.2273x over previous
#include <cuda_runtime.h>
#include <math.h>

#define T_ 100
#define B_ 64
#define I_ 256
#define H_ 512
#define G4_ (4*H_)   // 2048
#define H3_ (3*H_)   // 1536
#define BH_ (B_*H_)  // 32768
#define NBLK_ 128    // 4 batch-groups x 32 hidden-groups
#define BB_ 16       // batches per block
#define HH_ 16       // hidden cols per block
#define WD_STRIDE 65   // u64 per kp row (64 + 1 pad)
#define HS_STRIDE 258  // u64 per h-row (256 + 2 pad, keeps 16B alignment)

typedef unsigned long long u64;

// ---------------- scratch (device globals) -----------------------------------
__device__ float g_xproj[(size_t)T_*B_*G4_];   // [T*B][4H] input-path gates + biases
__device__ float g_hseq[(size_t)(T_+1)*BH_];   // hseq[t] = h_{t-1}; hseq[0]=h0
__device__ float g_f[(size_t)T_*BH_];          // forget gates
__device__ float g_d[(size_t)T_*B_*H3_];       // d_i|d_f|d_g; suffix-scaled in place
__device__ unsigned g_flags[NBLK_];            // per-block arrival step
__device__ unsigned g_go;                      // broadcast release step

// ---------------- helpers -----------------------------------------------------
__device__ __forceinline__ u64 pack2(float x, float y) {
    u64 r; asm("mov.b64 %0, {%1,%2};" : "=l"(r) : "f"(x), "f"(y)); return r;
}
__device__ __forceinline__ void unpack2(u64 v, float& x, float& y) {
    asm("mov.b64 {%0,%1}, %2;" : "=f"(x), "=f"(y) : "l"(v));
}
__device__ __forceinline__ u64 fma2(u64 a, u64 b, u64 c) {
    u64 d; asm("fma.rn.f32x2 %0, %1, %2, %3;" : "=l"(d) : "l"(a), "l"(b), "l"(c)); return d;
}
__device__ __forceinline__ u64 ldcg64(const u64* p) {
    u64 v; asm volatile("ld.global.cg.b64 %0, [%1];" : "=l"(v) : "l"(p)); return v;
}
__device__ __forceinline__ unsigned ldacq32(const unsigned* p) {
    unsigned v; asm volatile("ld.acquire.gpu.global.u32 %0, [%1];" : "=r"(v) : "l"(p)); return v;
}
__device__ __forceinline__ void strel32(unsigned* p, unsigned v) {
    asm volatile("st.release.gpu.global.u32 [%0], %1;" :: "l"(p), "r"(v) : "memory");
}

// ---------------- init --------------------------------------------------------
__global__ void k_init(const float* __restrict__ h0) {
    int i = blockIdx.x*256 + threadIdx.x;
    if (i < BH_) g_hseq[i] = h0[i];
    if (i < NBLK_) g_flags[i] = 0u;
    if (i == 0) g_go = 0u;
}

// ---------------- K1: xproj = X @ Wih^T + b_ih + b_hh (f32x2) -----------------
__global__ __launch_bounds__(256, 2) void k1_xproj(
    const float* __restrict__ X, const float* __restrict__ W,
    const float* __restrict__ bih, const float* __restrict__ bhh)
{
    __shared__ __align__(16) float As[8][132];
    __shared__ __align__(16) float Ws[8][132];
    int m0 = blockIdx.y * 128;
    int n0 = blockIdx.x * 128;
    int tid = threadIdx.x;
    int lc = tid % 8;
    int lr = tid / 8;
    int ty = tid / 16, tx = tid % 16;

    u64 acc2[8][4];
    #pragma unroll
    for (int i=0;i<8;i++)
        #pragma unroll
        for (int j=0;j<4;j++) acc2[i][j]=0ull;

    for (int k0 = 0; k0 < I_; k0 += 8) {
        #pragma unroll
        for (int p = 0; p < 4; p++) {
            int r = lr + p*32;
            As[lc][r] = X[(size_t)(m0 + r)*I_ + k0 + lc];
            Ws[lc][r] = W[(size_t)(n0 + r)*I_ + k0 + lc];
        }
        __syncthreads();
        #pragma unroll
        for (int kk = 0; kk < 8; kk++) {
            float4 a0 = *(const float4*)&As[kk][ty*4];
            float4 a1 = *(const float4*)&As[kk][64 + ty*4];
            ulonglong2 bv0 = *(const ulonglong2*)&Ws[kk][tx*4];
            ulonglong2 bv1 = *(const ulonglong2*)&Ws[kk][64 + tx*4];
            u64 bb[4] = {bv0.x, bv0.y, bv1.x, bv1.y};
            float a[8] = {a0.x,a0.y,a0.z,a0.w,a1.x,a1.y,a1.z,a1.w};
            #pragma unroll
            for (int i=0;i<8;i++) {
                u64 ad = pack2(a[i], a[i]);
                #pragma unroll
                for (int j=0;j<4;j++) acc2[i][j] = fma2(ad, bb[j], acc2[i][j]);
            }
        }
        __syncthreads();
    }
    float bias[8];
    #pragma unroll
    for (int j=0;j<8;j++) {
        int n = n0 + ((j<4)? tx*4 + j : 64 + tx*4 + (j-4));
        bias[j] = bih[n] + bhh[n];
    }
    #pragma unroll
    for (int i=0;i<8;i++) {
        int m = m0 + ((i<4)? ty*4+i : 64+ty*4+(i-4));
        float* row = g_xproj + (size_t)m*G4_ + n0;
        float c[8];
        unpack2(acc2[i][0], c[0], c[1]);
        unpack2(acc2[i][1], c[2], c[3]);
        unpack2(acc2[i][2], c[4], c[5]);
        unpack2(acc2[i][3], c[6], c[7]);
        float4 v0 = make_float4(c[0]+bias[0], c[1]+bias[1], c[2]+bias[2], c[3]+bias[3]);
        float4 v1 = make_float4(c[4]+bias[4], c[5]+bias[5], c[6]+bias[6], c[7]+bias[7]);
        *(float4*)&row[tx*4]      = v0;
        *(float4*)&row[64+tx*4]   = v1;
    }
}

// ---------------- persistent recurrence kernel v2 ------------------------------
// Block (bg, hgid): bg = bid>>5 (16 batches), hgid = bid&31 (16 hidden cols, all 4 gates).
// Smem: Wd [256 kp][65] u64 (W pairs, kp-major), hs [16 b][258] u64, exch [4][16][16] f.
// Thread GEMM role: q = tid&3, hl = (tid>>2)&15, bq = tid>>6 -> 4 outputs (4 batches).
// Thread pointwise role: pb = tid>>4, ph = tid&15 -> cell (bbase+pb, hbase+ph).
__global__ __launch_bounds__(256, 1) void k_rec(
    const float* __restrict__ Whh, const float* __restrict__ c0,
    float* __restrict__ out_h, float* __restrict__ out_cx)
{
    extern __shared__ u64 dsm[];
    u64*   Wd   = dsm;                               // 256*65
    u64*   hs   = dsm + 256*WD_STRIDE;               // 16*258
    float* exch = (float*)(dsm + 256*WD_STRIDE + BB_*HS_STRIDE);  // 1024 floats

    int bid = blockIdx.x;
    int tid = threadIdx.x;
    int bg    = bid >> 5;
    int hgid  = bid & 31;
    int bbase = bg * BB_;
    int hbase = hgid * HH_;

    // ---- W slice: Wd[kp][r], r = h*4+q  <->  Whh[q*512 + hbase + h][2kp..2kp+1]
    for (int r = 0; r < 64; r++) {
        int h = r >> 2, q = r & 3;
        const u64* src = (const u64*)(Whh + (size_t)(q*H_ + hbase + h)*H_);
        Wd[(size_t)tid*WD_STRIDE + r] = src[tid];
    }

    // pointwise ownership
    int pb = tid >> 4;
    int ph = tid & 15;
    int pbg = bbase + pb;           // global batch
    int phg = hbase + ph;           // global hidden col
    float c = c0[pbg*H_ + phg];

    // GEMM ownership
    int q   = tid & 3;
    int hl  = (tid >> 2) & 15;
    int bq  = tid >> 6;
    int hq  = tid & 63;             // = hl*4 + q
    (void)hl; (void)q;

    // copy-role indices
    int cb = tid >> 4;              // 0..15 local batch row
    int cc = tid & 15;              // 0..15 chunk

    __syncthreads();

    for (int t = 0; t < T_; ++t) {
        // ---- stage h slice (16 rows x 256 u64) from g_hseq[t] via L2 ----
        {
            const u64* hsrc = (const u64*)(g_hseq + (size_t)t*BH_ + (size_t)(bbase+cb)*H_);
            #pragma unroll
            for (int i = 0; i < 16; i++)
                hs[(size_t)cb*HS_STRIDE + cc + i*16] = ldcg64(&hsrc[cc + i*16]);
        }
        // hoisted xproj loads for pointwise
        const float* xp = g_xproj + ((size_t)t*B_ + pbg)*G4_;
        float xpi = xp[phg];
        float xpf = xp[H_+phg];
        float xpg = xp[2*H_+phg];
        float xpo = xp[3*H_+phg];
        __syncthreads();

        // ---- GEMM: 4 outputs per thread, even/odd k pairs via f32x2 ----
        u64 a0=0ull, a1=0ull, a2=0ull, a3=0ull;
        const u64* h0p = &hs[(size_t)(bq*4+0)*HS_STRIDE];
        const u64* h1p = &hs[(size_t)(bq*4+1)*HS_STRIDE];
        const u64* h2p = &hs[(size_t)(bq*4+2)*HS_STRIDE];
        const u64* h3p = &hs[(size_t)(bq*4+3)*HS_STRIDE];
        #pragma unroll 4
        for (int kp = 0; kp < 256; kp += 2) {
            u64 w0 = Wd[(size_t)kp*WD_STRIDE + hq];
            u64 w1 = Wd[(size_t)(kp+1)*WD_STRIDE + hq];
            ulonglong2 hv0 = *(const ulonglong2*)&h0p[kp];
            ulonglong2 hv1 = *(const ulonglong2*)&h1p[kp];
            ulonglong2 hv2 = *(const ulonglong2*)&h2p[kp];
            ulonglong2 hv3 = *(const ulonglong2*)&h3p[kp];
            a0 = fma2(hv0.x, w0, a0); a0 = fma2(hv0.y, w1, a0);
            a1 = fma2(hv1.x, w0, a1); a1 = fma2(hv1.y, w1, a1);
            a2 = fma2(hv2.x, w0, a2); a2 = fma2(hv2.y, w1, a2);
            a3 = fma2(hv3.x, w0, a3); a3 = fma2(hv3.y, w1, a3);
        }
        {
            float lo, hi;
            int qq = tid & 3, hh = (tid>>2)&15;
            unpack2(a0, lo, hi); exch[qq*256 + (bq*4+0)*16 + hh] = lo + hi;
            unpack2(a1, lo, hi); exch[qq*256 + (bq*4+1)*16 + hh] = lo + hi;
            unpack2(a2, lo, hi); exch[qq*256 + (bq*4+2)*16 + hh] = lo + hi;
            unpack2(a3, lo, hi); exch[qq*256 + (bq*4+3)*16 + hh] = lo + hi;
        }
        __syncthreads();

        // ---- pointwise for cell (pbg, phg) ----
        {
            float ai = xpi + exch[0*256 + pb*16 + ph];
            float af = xpf + exch[1*256 + pb*16 + ph];
            float ag = xpg + exch[2*256 + pb*16 + ph];
            float ao = xpo + exch[3*256 + pb*16 + ph];

            float ig = 1.f/(1.f+__expf(-ai));
            float fg = 1.f/(1.f+__expf(-af));
            float gg = tanhf(ag);
            float og = 1.f/(1.f+__expf(-ao));
            float cprev = c;
            float cy = fg*cprev + ig*gg;
            float hy = og*tanhf(cy);
            c = cy;

            size_t oidx = (size_t)t*BH_ + (size_t)pbg*H_ + phg;
            out_h[oidx] = hy;
            g_hseq[(size_t)(t+1)*BH_ + (size_t)pbg*H_ + phg] = hy;
            g_f[oidx] = fg;
            float* dp = g_d + ((size_t)t*B_ + pbg)*H3_;
            dp[phg]        = gg*ig*(1.f-ig);
            dp[H_+phg]     = cprev*fg*(1.f-fg);
            dp[2*H_+phg]   = ig*(1.f-gg*gg);
            if (t == T_-1) out_cx[pbg*H_ + phg] = cy;
        }

        // ---- grid barrier: per-block flags + single broadcaster (no hot atomics)
        __threadfence();
        __syncthreads();
        if (bid != 0) {
            if (tid == 0) strel32(&g_flags[bid], (unsigned)(t+1));
            if (tid == 0) { while (ldacq32(&g_go) < (unsigned)(t+1)) {} }
            __syncthreads();
        } else {
            if (tid >= 1 && tid < NBLK_) {
                while (ldacq32(&g_flags[tid]) < (unsigned)(t+1)) {}
            }
            __syncthreads();
            if (tid == 0) strel32(&g_go, (unsigned)(t+1));
        }
    }
}

// ---------------- K3: suffix forget-product scan; ev_b -------------------------
__global__ void k3_suffix(float* __restrict__ out_evb)
{
    int idx = blockIdx.x*256 + threadIdx.x;   // < BH_
    int b = idx >> 9;
    int h = idx & 511;
    float p = 1.f, s0 = 0.f, s1 = 0.f, s2 = 0.f;

    float* dpp = g_d + ((size_t)(T_-1)*B_ + b)*H3_;
    float di = dpp[h], df = dpp[H_+h], dg = dpp[2*H_+h];
    float fv = g_f[(size_t)(T_-1)*BH_ + idx];

    for (int t = T_-1; t >= 0; --t) {
        float cdi = di, cdf = df, cdg = dg, cf = fv;
        float* dpc = g_d + ((size_t)t*B_ + b)*H3_;
        if (t > 0) {
            float* dpn = g_d + ((size_t)(t-1)*B_ + b)*H3_;
            di = dpn[h]; df = dpn[H_+h]; dg = dpn[2*H_+h];
            fv = g_f[(size_t)(t-1)*BH_ + idx];
        }
        float wi = cdi*p, wf = cdf*p, wg = cdg*p;
        dpc[h] = wi; dpc[H_+h] = wf; dpc[2*H_+h] = wg;
        s0 += wi; s1 += wf; s2 += wg;
        p *= cf;
    }
    out_evb[(size_t)b*H3_ + h]        = s0;
    out_evb[(size_t)b*H3_ + H_ + h]   = s1;
    out_evb[(size_t)b*H3_ + 2*H_ + h] = s2;
}

// ---------------- K4/K5: batched ev GEMM (f32x2) ------------------------------
__global__ __launch_bounds__(256, 2) void k_ev(
    const float* __restrict__ Xin, float* __restrict__ C, int Idim)
{
    __shared__ __align__(16) float As[8][132];
    __shared__ __align__(16) float Xs[8][132];
    const float* X = Xin ? Xin : (const float*)g_hseq;
    int i0 = blockIdx.x*128;
    int j0 = blockIdx.y*128;
    int b  = blockIdx.z;
    int tid = threadIdx.x;
    int ty = tid/16, tx = tid%16;
    int lk = tid >> 5;
    int lj = (tid & 31) * 4;

    u64 acc2[8][4];
    #pragma unroll
    for (int i=0;i<8;i++)
        #pragma unroll
        for (int j=0;j<4;j++) acc2[i][j]=0ull;

    for (int t0 = 0; t0 < T_; t0 += 8) {
        int t = t0 + lk;
        if (t < T_) {
            *(float4*)&As[lk][lj] = *(const float4*)&g_d[((size_t)t*B_+b)*H3_ + j0 + lj];
            *(float4*)&Xs[lk][lj] = *(const float4*)&X[((size_t)t*B_+b)*Idim + i0 + lj];
        } else {
            float4 z = make_float4(0.f,0.f,0.f,0.f);
            *(float4*)&As[lk][lj] = z;
            *(float4*)&Xs[lk][lj] = z;
        }
        __syncthreads();
        #pragma unroll
        for (int kk=0;kk<8;kk++) {
            float4 a0 = *(const float4*)&As[kk][ty*4];
            float4 a1 = *(const float4*)&As[kk][64+ty*4];
            ulonglong2 xv0 = *(const ulonglong2*)&Xs[kk][tx*4];
            ulonglong2 xv1 = *(const ulonglong2*)&Xs[kk][64+tx*4];
            u64 xx[4] = {xv0.x, xv0.y, xv1.x, xv1.y};
            float a[8] = {a0.x,a0.y,a0.z,a0.w,a1.x,a1.y,a1.z,a1.w};
            #pragma unroll
            for (int i=0;i<8;i++) {
                u64 ad = pack2(a[i], a[i]);
                #pragma unroll
                for (int j=0;j<4;j++) acc2[i][j] = fma2(ad, xx[j], acc2[i][j]);
            }
        }
        __syncthreads();
    }
    #pragma unroll
    for (int i=0;i<8;i++) {
        int j = j0 + ((i<4)? ty*4+i : 64+ty*4+(i-4));
        float* row = C + (size_t)b*H3_*Idim + (size_t)j*Idim + i0;
        float cr[8];
        unpack2(acc2[i][0], cr[0], cr[1]);
        unpack2(acc2[i][1], cr[2], cr[3]);
        unpack2(acc2[i][2], cr[4], cr[5]);
        unpack2(acc2[i][3], cr[6], cr[7]);
        *(float4*)&row[tx*4]    = make_float4(cr[0],cr[1],cr[2],cr[3]);
        *(float4*)&row[64+tx*4] = make_float4(cr[4],cr[5],cr[6],cr[7]);
    }
}

// ---------------- launch -------------------------------------------------------
extern "C" void kernel_launch(void* const* d_in, const int* in_sizes, int n_in,
                              void* d_out, int out_size)
{
    const float* input = (const float*)d_in[0];
    const float* h0    = (const float*)d_in[1];
    const float* c0    = (const float*)d_in[2];
    const float* Wih   = (const float*)d_in[3];
    const float* Whh   = (const float*)d_in[4];
    const float* bih   = (const float*)d_in[5];
    const float* bhh   = (const float*)d_in[6];

    float* out      = (float*)d_out;
    float* out_h    = out;
    float* out_cx   = out_h  + (size_t)T_*BH_;
    float* out_evih = out_cx + BH_;
    float* out_evhh = out_evih + (size_t)B_*H3_*I_;
    float* out_evb  = out_evhh + (size_t)B_*H3_*H_;

    const int dyn_smem = (256*WD_STRIDE + BB_*HS_STRIDE)*8 + 1024*4;  // ~167 KB
    cudaFuncSetAttribute(k_rec, cudaFuncAttributeMaxDynamicSharedMemorySize, dyn_smem);

    k_init<<<128,256>>>(h0);
    k1_xproj<<<dim3(16,50),256>>>(input, Wih, bih, bhh);
    k_rec<<<NBLK_, 256, dyn_smem>>>(Whh, c0, out_h, out_cx);
    k3_suffix<<<128,256>>>(out_evb);
    k_ev<<<dim3(I_/128, H3_/128, B_),256>>>(input, out_evih, I_);
    k_ev<<<dim3(H_/128, H3_/128, B_),256>>>(nullptr, out_evhh, H_);
}

// round 14
// speedup vs baseline: 1.2837x; 1.0460x over previous
#include <cuda_runtime.h>
#include <math.h>

#define T_ 100
#define B_ 64
#define I_ 256
#define H_ 512
#define G4_ (4*H_)   // 2048
#define H3_ (3*H_)   // 1536
#define BH_ (B_*H_)  // 32768
#define NBLK_ 128    // 4 batch-groups x 32 hidden-groups
#define BB_ 16       // batches per block
#define HH_ 16       // hidden cols per block
#define WD_STRIDE 65   // u64 per kp row (64 + 1 pad)
#define HS_STRIDE 258  // u64 per h-row (256 + 2 pad, keeps 16B alignment)

typedef unsigned long long u64;

// ---------------- scratch (device globals) -----------------------------------
__device__ float g_xproj[(size_t)T_*B_*G4_];   // [T*B][4H] input-path gates + biases
__device__ float g_hseq[(size_t)(T_+1)*BH_];   // hseq[t] = h_{t-1}; hseq[0]=h0
__device__ float g_f[(size_t)T_*BH_];          // forget gates
__device__ float g_d[(size_t)T_*B_*H3_];       // d_i|d_f|d_g; suffix-scaled in place
__device__ unsigned g_flags[NBLK_];            // per-block arrival step
__device__ unsigned g_go4[4];                  // per-batch-group release step

// ---------------- helpers -----------------------------------------------------
__device__ __forceinline__ u64 pack2(float x, float y) {
    u64 r; asm("mov.b64 %0, {%1,%2};" : "=l"(r) : "f"(x), "f"(y)); return r;
}
__device__ __forceinline__ void unpack2(u64 v, float& x, float& y) {
    asm("mov.b64 {%0,%1}, %2;" : "=f"(x), "=f"(y) : "l"(v));
}
__device__ __forceinline__ u64 fma2(u64 a, u64 b, u64 c) {
    u64 d; asm("fma.rn.f32x2 %0, %1, %2, %3;" : "=l"(d) : "l"(a), "l"(b), "l"(c)); return d;
}
__device__ __forceinline__ u64 ldcg64(const u64* p) {
    u64 v; asm volatile("ld.global.cg.b64 %0, [%1];" : "=l"(v) : "l"(p)); return v;
}
__device__ __forceinline__ unsigned ldacq32(const unsigned* p) {
    unsigned v; asm volatile("ld.acquire.gpu.global.u32 %0, [%1];" : "=r"(v) : "l"(p)); return v;
}
__device__ __forceinline__ void strel32(unsigned* p, unsigned v) {
    asm volatile("st.release.gpu.global.u32 [%0], %1;" :: "l"(p), "r"(v) : "memory");
}
__device__ __forceinline__ float sigf(float x) {
    return __fdividef(1.f, 1.f + __expf(-x));
}

// ---------------- init --------------------------------------------------------
__global__ void k_init(const float* __restrict__ h0) {
    int i = blockIdx.x*256 + threadIdx.x;
    if (i < BH_) g_hseq[i] = h0[i];
    if (i < NBLK_) g_flags[i] = 0u;
    if (i < 4) g_go4[i] = 0u;
}

// ---------------- K1: xproj = X @ Wih^T + b_ih + b_hh (f32x2, reg-DB) ---------
__global__ __launch_bounds__(256, 2) void k1_xproj(
    const float* __restrict__ X, const float* __restrict__ W,
    const float* __restrict__ bih, const float* __restrict__ bhh)
{
    __shared__ __align__(16) float As[8][132];
    __shared__ __align__(16) float Ws[8][132];
    int m0 = blockIdx.y * 128;
    int n0 = blockIdx.x * 128;
    int tid = threadIdx.x;
    int lc = tid % 8;
    int lr = tid / 8;
    int ty = tid / 16, tx = tid % 16;

    u64 acc2[8][4];
    #pragma unroll
    for (int i=0;i<8;i++)
        #pragma unroll
        for (int j=0;j<4;j++) acc2[i][j]=0ull;

    float ra[4], rw[4];
    #pragma unroll
    for (int p = 0; p < 4; p++) {
        int r = lr + p*32;
        ra[p] = X[(size_t)(m0 + r)*I_ + lc];
        rw[p] = W[(size_t)(n0 + r)*I_ + lc];
    }

    for (int k0 = 0; k0 < I_; k0 += 8) {
        #pragma unroll
        for (int p = 0; p < 4; p++) {
            int r = lr + p*32;
            As[lc][r] = ra[p];
            Ws[lc][r] = rw[p];
        }
        __syncthreads();
        if (k0 + 8 < I_) {
            #pragma unroll
            for (int p = 0; p < 4; p++) {
                int r = lr + p*32;
                ra[p] = X[(size_t)(m0 + r)*I_ + k0 + 8 + lc];
                rw[p] = W[(size_t)(n0 + r)*I_ + k0 + 8 + lc];
            }
        }
        #pragma unroll
        for (int kk = 0; kk < 8; kk++) {
            float4 a0 = *(const float4*)&As[kk][ty*4];
            float4 a1 = *(const float4*)&As[kk][64 + ty*4];
            ulonglong2 bv0 = *(const ulonglong2*)&Ws[kk][tx*4];
            ulonglong2 bv1 = *(const ulonglong2*)&Ws[kk][64 + tx*4];
            u64 bb[4] = {bv0.x, bv0.y, bv1.x, bv1.y};
            float a[8] = {a0.x,a0.y,a0.z,a0.w,a1.x,a1.y,a1.z,a1.w};
            #pragma unroll
            for (int i=0;i<8;i++) {
                u64 ad = pack2(a[i], a[i]);
                #pragma unroll
                for (int j=0;j<4;j++) acc2[i][j] = fma2(ad, bb[j], acc2[i][j]);
            }
        }
        __syncthreads();
    }
    float bias[8];
    #pragma unroll
    for (int j=0;j<8;j++) {
        int n = n0 + ((j<4)? tx*4 + j : 64 + tx*4 + (j-4));
        bias[j] = bih[n] + bhh[n];
    }
    #pragma unroll
    for (int i=0;i<8;i++) {
        int m = m0 + ((i<4)? ty*4+i : 64+ty*4+(i-4));
        float* row = g_xproj + (size_t)m*G4_ + n0;
        float c[8];
        unpack2(acc2[i][0], c[0], c[1]);
        unpack2(acc2[i][1], c[2], c[3]);
        unpack2(acc2[i][2], c[4], c[5]);
        unpack2(acc2[i][3], c[6], c[7]);
        float4 v0 = make_float4(c[0]+bias[0], c[1]+bias[1], c[2]+bias[2], c[3]+bias[3]);
        float4 v1 = make_float4(c[4]+bias[4], c[5]+bias[5], c[6]+bias[6], c[7]+bias[7]);
        *(float4*)&row[tx*4]      = v0;
        *(float4*)&row[64+tx*4]   = v1;
    }
}

// ---------------- persistent recurrence kernel v2 + group barriers -------------
__global__ __launch_bounds__(256, 1) void k_rec(
    const float* __restrict__ Whh, const float* __restrict__ c0,
    float* __restrict__ out_h, float* __restrict__ out_cx)
{
    extern __shared__ u64 dsm[];
    u64*   Wd   = dsm;                               // 256*65
    u64*   hs   = dsm + 256*WD_STRIDE;               // 16*258
    float* exch = (float*)(dsm + 256*WD_STRIDE + BB_*HS_STRIDE);  // 1024 floats

    int bid = blockIdx.x;
    int tid = threadIdx.x;
    int bg    = bid >> 5;
    int hgid  = bid & 31;
    int bbase = bg * BB_;
    int hbase = hgid * HH_;
    int grpbase = bg << 5;

    // ---- W slice: Wd[kp][r], r = h*4+q  <->  Whh[q*512 + hbase + h][2kp..2kp+1]
    for (int r = 0; r < 64; r++) {
        int h = r >> 2, q = r & 3;
        const u64* src = (const u64*)(Whh + (size_t)(q*H_ + hbase + h)*H_);
        Wd[(size_t)tid*WD_STRIDE + r] = src[tid];
    }

    // pointwise ownership
    int pb = tid >> 4;
    int ph = tid & 15;
    int pbg = bbase + pb;
    int phg = hbase + ph;
    float c = c0[pbg*H_ + phg];

    // GEMM ownership
    int bq  = tid >> 6;
    int hq  = tid & 63;

    // copy-role indices
    int cb = tid >> 4;
    int cc = tid & 15;

    __syncthreads();

    for (int t = 0; t < T_; ++t) {
        // ---- stage h slice (16 rows x 256 u64) from g_hseq[t] via L2 ----
        {
            const u64* hsrc = (const u64*)(g_hseq + (size_t)t*BH_ + (size_t)(bbase+cb)*H_);
            #pragma unroll
            for (int i = 0; i < 16; i++)
                hs[(size_t)cb*HS_STRIDE + cc + i*16] = ldcg64(&hsrc[cc + i*16]);
        }
        const float* xp = g_xproj + ((size_t)t*B_ + pbg)*G4_;
        float xpi = xp[phg];
        float xpf = xp[H_+phg];
        float xpg = xp[2*H_+phg];
        float xpo = xp[3*H_+phg];
        __syncthreads();

        // ---- GEMM: 4 outputs per thread, even/odd k pairs via f32x2 ----
        u64 a0=0ull, a1=0ull, a2=0ull, a3=0ull;
        const u64* h0p = &hs[(size_t)(bq*4+0)*HS_STRIDE];
        const u64* h1p = &hs[(size_t)(bq*4+1)*HS_STRIDE];
        const u64* h2p = &hs[(size_t)(bq*4+2)*HS_STRIDE];
        const u64* h3p = &hs[(size_t)(bq*4+3)*HS_STRIDE];
        #pragma unroll 4
        for (int kp = 0; kp < 256; kp += 2) {
            u64 w0 = Wd[(size_t)kp*WD_STRIDE + hq];
            u64 w1 = Wd[(size_t)(kp+1)*WD_STRIDE + hq];
            ulonglong2 hv0 = *(const ulonglong2*)&h0p[kp];
            ulonglong2 hv1 = *(const ulonglong2*)&h1p[kp];
            ulonglong2 hv2 = *(const ulonglong2*)&h2p[kp];
            ulonglong2 hv3 = *(const ulonglong2*)&h3p[kp];
            a0 = fma2(hv0.x, w0, a0); a0 = fma2(hv0.y, w1, a0);
            a1 = fma2(hv1.x, w0, a1); a1 = fma2(hv1.y, w1, a1);
            a2 = fma2(hv2.x, w0, a2); a2 = fma2(hv2.y, w1, a2);
            a3 = fma2(hv3.x, w0, a3); a3 = fma2(hv3.y, w1, a3);
        }
        {
            float lo, hi;
            int qq = tid & 3, hh = (tid>>2)&15;
            unpack2(a0, lo, hi); exch[qq*256 + (bq*4+0)*16 + hh] = lo + hi;
            unpack2(a1, lo, hi); exch[qq*256 + (bq*4+1)*16 + hh] = lo + hi;
            unpack2(a2, lo, hi); exch[qq*256 + (bq*4+2)*16 + hh] = lo + hi;
            unpack2(a3, lo, hi); exch[qq*256 + (bq*4+3)*16 + hh] = lo + hi;
        }
        __syncthreads();

        // ---- pointwise for cell (pbg, phg) ----
        {
            float ai = xpi + exch[0*256 + pb*16 + ph];
            float af = xpf + exch[1*256 + pb*16 + ph];
            float ag = xpg + exch[2*256 + pb*16 + ph];
            float ao = xpo + exch[3*256 + pb*16 + ph];

            float ig = sigf(ai);
            float fg = sigf(af);
            float gg = __tanhf(ag);
            float og = sigf(ao);
            float cprev = c;
            float cy = fg*cprev + ig*gg;
            float hy = og*__tanhf(cy);
            c = cy;

            size_t oidx = (size_t)t*BH_ + (size_t)pbg*H_ + phg;
            out_h[oidx] = hy;
            g_hseq[(size_t)(t+1)*BH_ + (size_t)pbg*H_ + phg] = hy;
            g_f[oidx] = fg;
            float* dp = g_d + ((size_t)t*B_ + pbg)*H3_;
            dp[phg]        = gg*ig*(1.f-ig);
            dp[H_+phg]     = cprev*fg*(1.f-fg);
            dp[2*H_+phg]   = ig*(1.f-gg*gg);
            if (t == T_-1) out_cx[pbg*H_ + phg] = cy;
        }

        // ---- per-batch-group barrier (32 blocks; batches are independent) ----
        __threadfence();
        __syncthreads();
        if (bid != grpbase) {
            if (tid == 0) {
                strel32(&g_flags[bid], (unsigned)(t+1));
                while (ldacq32(&g_go4[bg]) < (unsigned)(t+1)) {}
            }
            __syncthreads();
        } else {
            if (tid >= 1 && tid < 32) {
                while (ldacq32(&g_flags[grpbase + tid]) < (unsigned)(t+1)) {}
            }
            __syncthreads();
            if (tid == 0) strel32(&g_go4[bg], (unsigned)(t+1));
        }
    }
}

// ---------------- K3: suffix forget-product scan (prefetch-4); ev_b -----------
__global__ void k3_suffix(float* __restrict__ out_evb)
{
    int idx = blockIdx.x*256 + threadIdx.x;   // < BH_
    int b = idx >> 9;
    int h = idx & 511;
    float p = 1.f, s0 = 0.f, s1 = 0.f, s2 = 0.f;

    float pdi[4], pdf[4], pdg[4], pfv[4];
    #pragma unroll
    for (int s = 0; s < 4; s++) {
        const float* dp = g_d + ((size_t)(T_-1-s)*B_ + b)*H3_;
        pdi[s] = dp[h]; pdf[s] = dp[H_+h]; pdg[s] = dp[2*H_+h];
        pfv[s] = g_f[(size_t)(T_-1-s)*BH_ + idx];
    }

    for (int tb = T_-1; tb >= 3; tb -= 4) {
        #pragma unroll
        for (int s = 0; s < 4; s++) {
            int t = tb - s;
            float cdi = pdi[s], cdf = pdf[s], cdg = pdg[s], cf = pfv[s];
            if (t >= 4) {
                const float* dn = g_d + ((size_t)(t-4)*B_ + b)*H3_;
                pdi[s] = dn[h]; pdf[s] = dn[H_+h]; pdg[s] = dn[2*H_+h];
                pfv[s] = g_f[(size_t)(t-4)*BH_ + idx];
            }
            float* dpc = g_d + ((size_t)t*B_ + b)*H3_;
            float wi = cdi*p, wf = cdf*p, wg = cdg*p;
            dpc[h] = wi; dpc[H_+h] = wf; dpc[2*H_+h] = wg;
            s0 += wi; s1 += wf; s2 += wg;
            p *= cf;
        }
    }
    out_evb[(size_t)b*H3_ + h]        = s0;
    out_evb[(size_t)b*H3_ + H_ + h]   = s1;
    out_evb[(size_t)b*H3_ + 2*H_ + h] = s2;
}

// ---------------- K4/K5: batched ev GEMM (f32x2, reg-DB) ----------------------
__global__ __launch_bounds__(256, 2) void k_ev(
    const float* __restrict__ Xin, float* __restrict__ C, int Idim)
{
    __shared__ __align__(16) float As[8][132];
    __shared__ __align__(16) float Xs[8][132];
    const float* X = Xin ? Xin : (const float*)g_hseq;
    int i0 = blockIdx.x*128;
    int j0 = blockIdx.y*128;
    int b  = blockIdx.z;
    int tid = threadIdx.x;
    int ty = tid/16, tx = tid%16;
    int lk = tid >> 5;
    int lj = (tid & 31) * 4;

    u64 acc2[8][4];
    #pragma unroll
    for (int i=0;i<8;i++)
        #pragma unroll
        for (int j=0;j<4;j++) acc2[i][j]=0ull;

    float4 rA, rX;
    {
        int t = lk;
        rA = *(const float4*)&g_d[((size_t)t*B_+b)*H3_ + j0 + lj];
        rX = *(const float4*)&X[((size_t)t*B_+b)*Idim + i0 + lj];
    }

    for (int t0 = 0; t0 < T_; t0 += 8) {
        *(float4*)&As[lk][lj] = rA;
        *(float4*)&Xs[lk][lj] = rX;
        __syncthreads();
        {
            int tn = t0 + 8 + lk;
            if (tn < T_) {
                rA = *(const float4*)&g_d[((size_t)tn*B_+b)*H3_ + j0 + lj];
                rX = *(const float4*)&X[((size_t)tn*B_+b)*Idim + i0 + lj];
            } else {
                rA = make_float4(0.f,0.f,0.f,0.f);
                rX = make_float4(0.f,0.f,0.f,0.f);
            }
        }
        #pragma unroll
        for (int kk=0;kk<8;kk++) {
            if (t0 + kk >= T_) break;
            float4 a0 = *(const float4*)&As[kk][ty*4];
            float4 a1 = *(const float4*)&As[kk][64+ty*4];
            ulonglong2 xv0 = *(const ulonglong2*)&Xs[kk][tx*4];
            ulonglong2 xv1 = *(const ulonglong2*)&Xs[kk][64+tx*4];
            u64 xx[4] = {xv0.x, xv0.y, xv1.x, xv1.y};
            float a[8] = {a0.x,a0.y,a0.z,a0.w,a1.x,a1.y,a1.z,a1.w};
            #pragma unroll
            for (int i=0;i<8;i++) {
                u64 ad = pack2(a[i], a[i]);
                #pragma unroll
                for (int j=0;j<4;j++) acc2[i][j] = fma2(ad, xx[j], acc2[i][j]);
            }
        }
        __syncthreads();
    }
    #pragma unroll
    for (int i=0;i<8;i++) {
        int j = j0 + ((i<4)? ty*4+i : 64+ty*4+(i-4));
        float* row = C + (size_t)b*H3_*Idim + (size_t)j*Idim + i0;
        float cr[8];
        unpack2(acc2[i][0], cr[0], cr[1]);
        unpack2(acc2[i][1], cr[2], cr[3]);
        unpack2(acc2[i][2], cr[4], cr[5]);
        unpack2(acc2[i][3], cr[6], cr[7]);
        *(float4*)&row[tx*4]    = make_float4(cr[0],cr[1],cr[2],cr[3]);
        *(float4*)&row[64+tx*4] = make_float4(cr[4],cr[5],cr[6],cr[7]);
    }
}

// ---------------- launch -------------------------------------------------------
extern "C" void kernel_launch(void* const* d_in, const int* in_sizes, int n_in,
                              void* d_out, int out_size)
{
    const float* input = (const float*)d_in[0];
    const float* h0    = (const float*)d_in[1];
    const float* c0    = (const float*)d_in[2];
    const float* Wih   = (const float*)d_in[3];
    const float* Whh   = (const float*)d_in[4];
    const float* bih   = (const float*)d_in[5];
    const float* bhh   = (const float*)d_in[6];

    float* out      = (float*)d_out;
    float* out_h    = out;
    float* out_cx   = out_h  + (size_t)T_*BH_;
    float* out_evih = out_cx + BH_;
    float* out_evhh = out_evih + (size_t)B_*H3_*I_;
    float* out_evb  = out_evhh + (size_t)B_*H3_*H_;

    const int dyn_smem = (256*WD_STRIDE + BB_*HS_STRIDE)*8 + 1024*4;  // ~167 KB
    cudaFuncSetAttribute(k_rec, cudaFuncAttributeMaxDynamicSharedMemorySize, dyn_smem);

    k_init<<<128,256>>>(h0);
    k1_xproj<<<dim3(16,50),256>>>(input, Wih, bih, bhh);
    k_rec<<<NBLK_, 256, dyn_smem>>>(Whh, c0, out_h, out_cx);
    k3_suffix<<<128,256>>>(out_evb);
    k_ev<<<dim3(I_/128, H3_/128, B_),256>>>(input, out_evih, I_);
    k_ev<<<dim3(H_/128, H3_/128, B_),256>>>(nullptr, out_evhh, H_);
}

// round 15
// speedup vs baseline: 1.3296x; 1.0358x over previous
#include <cuda_runtime.h>
#include <math.h>

#define T_ 100
#define B_ 64
#define I_ 256
#define H_ 512
#define G4_ (4*H_)   // 2048
#define H3_ (3*H_)   // 1536
#define BH_ (B_*H_)  // 32768
#define NBLK_ 128    // 4 batch-groups x 32 hidden-groups
#define BB_ 16       // batches per block
#define HH_ 16       // hidden cols per block
#define WD2 66       // u64 per kp row (64 + 2 pad; keeps rows 16B-aligned)
#define HS_STRIDE 258  // u64 per h-row (256 + 2 pad, 16B-aligned rows)

typedef unsigned long long u64;

// ---------------- scratch (device globals) -----------------------------------
__device__ float g_xproj[(size_t)T_*B_*G4_];   // [T*B][4H] input-path gates + biases
__device__ float g_hseq[(size_t)(T_+1)*BH_];   // hseq[t] = h_{t-1}; hseq[0]=h0
__device__ float g_f[(size_t)T_*BH_];          // forget gates
__device__ float g_d[(size_t)T_*B_*H3_];       // d_i|d_f|d_g; suffix-scaled in place
__device__ unsigned g_flags[NBLK_];            // per-block arrival step
__device__ unsigned g_go4[4];                  // per-batch-group release step

// ---------------- helpers -----------------------------------------------------
__device__ __forceinline__ u64 pack2(float x, float y) {
    u64 r; asm("mov.b64 %0, {%1,%2};" : "=l"(r) : "f"(x), "f"(y)); return r;
}
__device__ __forceinline__ void unpack2(u64 v, float& x, float& y) {
    asm("mov.b64 {%0,%1}, %2;" : "=f"(x), "=f"(y) : "l"(v));
}
__device__ __forceinline__ u64 fma2(u64 a, u64 b, u64 c) {
    u64 d; asm("fma.rn.f32x2 %0, %1, %2, %3;" : "=l"(d) : "l"(a), "l"(b), "l"(c)); return d;
}
__device__ __forceinline__ u64 ldcg64(const u64* p) {
    u64 v; asm volatile("ld.global.cg.b64 %0, [%1];" : "=l"(v) : "l"(p)); return v;
}
__device__ __forceinline__ unsigned ldacq32(const unsigned* p) {
    unsigned v; asm volatile("ld.acquire.gpu.global.u32 %0, [%1];" : "=r"(v) : "l"(p)); return v;
}
__device__ __forceinline__ void strel32(unsigned* p, unsigned v) {
    asm volatile("st.release.gpu.global.u32 [%0], %1;" :: "l"(p), "r"(v) : "memory");
}
__device__ __forceinline__ float sigf(float x) {
    return __fdividef(1.f, 1.f + __expf(-x));
}

// ---------------- init --------------------------------------------------------
__global__ void k_init(const float* __restrict__ h0) {
    int i = blockIdx.x*256 + threadIdx.x;
    if (i < BH_) g_hseq[i] = h0[i];
    if (i < NBLK_) g_flags[i] = 0u;
    if (i < 4) g_go4[i] = 0u;
}

// ---------------- K1: xproj = X @ Wih^T + b_ih + b_hh (f32x2, reg-DB) ---------
__global__ __launch_bounds__(256, 2) void k1_xproj(
    const float* __restrict__ X, const float* __restrict__ W,
    const float* __restrict__ bih, const float* __restrict__ bhh)
{
    __shared__ __align__(16) float As[8][132];
    __shared__ __align__(16) float Ws[8][132];
    int m0 = blockIdx.y * 128;
    int n0 = blockIdx.x * 128;
    int tid = threadIdx.x;
    int lc = tid % 8;
    int lr = tid / 8;
    int ty = tid / 16, tx = tid % 16;

    u64 acc2[8][4];
    #pragma unroll
    for (int i=0;i<8;i++)
        #pragma unroll
        for (int j=0;j<4;j++) acc2[i][j]=0ull;

    float ra[4], rw[4];
    #pragma unroll
    for (int p = 0; p < 4; p++) {
        int r = lr + p*32;
        ra[p] = X[(size_t)(m0 + r)*I_ + lc];
        rw[p] = W[(size_t)(n0 + r)*I_ + lc];
    }

    for (int k0 = 0; k0 < I_; k0 += 8) {
        #pragma unroll
        for (int p = 0; p < 4; p++) {
            int r = lr + p*32;
            As[lc][r] = ra[p];
            Ws[lc][r] = rw[p];
        }
        __syncthreads();
        if (k0 + 8 < I_) {
            #pragma unroll
            for (int p = 0; p < 4; p++) {
                int r = lr + p*32;
                ra[p] = X[(size_t)(m0 + r)*I_ + k0 + 8 + lc];
                rw[p] = W[(size_t)(n0 + r)*I_ + k0 + 8 + lc];
            }
        }
        #pragma unroll
        for (int kk = 0; kk < 8; kk++) {
            float4 a0 = *(const float4*)&As[kk][ty*4];
            float4 a1 = *(const float4*)&As[kk][64 + ty*4];
            ulonglong2 bv0 = *(const ulonglong2*)&Ws[kk][tx*4];
            ulonglong2 bv1 = *(const ulonglong2*)&Ws[kk][64 + tx*4];
            u64 bb[4] = {bv0.x, bv0.y, bv1.x, bv1.y};
            float a[8] = {a0.x,a0.y,a0.z,a0.w,a1.x,a1.y,a1.z,a1.w};
            #pragma unroll
            for (int i=0;i<8;i++) {
                u64 ad = pack2(a[i], a[i]);
                #pragma unroll
                for (int j=0;j<4;j++) acc2[i][j] = fma2(ad, bb[j], acc2[i][j]);
            }
        }
        __syncthreads();
    }
    float bias[8];
    #pragma unroll
    for (int j=0;j<8;j++) {
        int n = n0 + ((j<4)? tx*4 + j : 64 + tx*4 + (j-4));
        bias[j] = bih[n] + bhh[n];
    }
    #pragma unroll
    for (int i=0;i<8;i++) {
        int m = m0 + ((i<4)? ty*4+i : 64+ty*4+(i-4));
        float* row = g_xproj + (size_t)m*G4_ + n0;
        float c[8];
        unpack2(acc2[i][0], c[0], c[1]);
        unpack2(acc2[i][1], c[2], c[3]);
        unpack2(acc2[i][2], c[4], c[5]);
        unpack2(acc2[i][3], c[6], c[7]);
        float4 v0 = make_float4(c[0]+bias[0], c[1]+bias[1], c[2]+bias[2], c[3]+bias[3]);
        float4 v1 = make_float4(c[4]+bias[4], c[5]+bias[5], c[6]+bias[6], c[7]+bias[7]);
        *(float4*)&row[tx*4]      = v0;
        *(float4*)&row[64+tx*4]   = v1;
    }
}

// ---------------- persistent recurrence kernel v3 ------------------------------
// Block (bg, hgid). Thread GEMM role: ks = tid>>6 (k-quarter), bgrp = (tid>>4)&3,
// hloc = tid&15 -> computes 4 gates x 4 batches of hidden col hloc over 128 k.
// Exchange exch[q][b][h][ks]; pointwise reads float4 per gate + horizontal add.
__global__ __launch_bounds__(256, 1) void k_rec(
    const float* __restrict__ Whh, const float* __restrict__ c0,
    float* __restrict__ out_h, float* __restrict__ out_cx)
{
    extern __shared__ u64 dsm[];
    u64*   Wd   = dsm;                               // [256 kp][66]; cols r=h*4+q
    u64*   hs   = dsm + 256*WD2;                     // [16 b][258]
    float* exch = (float*)(dsm + 256*WD2 + BB_*HS_STRIDE);  // 4096 floats

    int bid = blockIdx.x;
    int tid = threadIdx.x;
    int bg    = bid >> 5;
    int hgid  = bid & 31;
    int bbase = bg * BB_;
    int hbase = hgid * HH_;
    int grpbase = bg << 5;

    // ---- W fill: tid = kp; Wd[kp][r] = (Whh[q*512+hbase+h][2kp], ..[2kp+1])
    {
        int kp = tid;
        for (int r = 0; r < 64; r++) {
            int h = r >> 2, q = r & 3;
            const u64* src = (const u64*)(Whh + (size_t)(q*H_ + hbase + h)*H_);
            Wd[(size_t)kp*WD2 + r] = src[kp];
        }
    }

    // pointwise ownership
    int pb = tid >> 4;
    int ph = tid & 15;
    int pbg = bbase + pb;
    int phg = hbase + ph;
    float c = c0[pbg*H_ + phg];

    // GEMM ownership
    int ks   = tid >> 6;
    int rem  = tid & 63;
    int bgrp = rem >> 4;
    int hloc = rem & 15;
    int kp0  = ks * 64;

    // copy-role indices
    int cb = tid >> 4;
    int cc = tid & 15;

    __syncthreads();

    for (int t = 0; t < T_; ++t) {
        // ---- stage h slice (16 rows x 256 u64) from g_hseq[t] via L2 ----
        {
            const u64* hsrc = (const u64*)(g_hseq + (size_t)t*BH_ + (size_t)(bbase+cb)*H_);
            #pragma unroll
            for (int i = 0; i < 16; i++)
                hs[(size_t)cb*HS_STRIDE + cc + i*16] = ldcg64(&hsrc[cc + i*16]);
        }
        const float* xp = g_xproj + ((size_t)t*B_ + pbg)*G4_;
        float xpi = xp[phg];
        float xpf = xp[H_+phg];
        float xpg = xp[2*H_+phg];
        float xpo = xp[3*H_+phg];
        __syncthreads();

        // ---- GEMM: 16 outputs/thread (4 gates x 4 batches), k-quarter ----
        u64 acc[4][4];   // [q][b]
        #pragma unroll
        for (int q=0;q<4;q++)
            #pragma unroll
            for (int b=0;b<4;b++) acc[q][b]=0ull;

        #pragma unroll 2
        for (int kp = kp0; kp < kp0 + 64; kp += 2) {
            ulonglong2 wA0 = *(const ulonglong2*)&Wd[(size_t)kp*WD2 + hloc*4];
            ulonglong2 wA1 = *(const ulonglong2*)&Wd[(size_t)kp*WD2 + hloc*4 + 2];
            ulonglong2 wB0 = *(const ulonglong2*)&Wd[(size_t)(kp+1)*WD2 + hloc*4];
            ulonglong2 wB1 = *(const ulonglong2*)&Wd[(size_t)(kp+1)*WD2 + hloc*4 + 2];
            #pragma unroll
            for (int b = 0; b < 4; b++) {
                ulonglong2 hv = *(const ulonglong2*)&hs[(size_t)(bgrp*4+b)*HS_STRIDE + kp];
                acc[0][b] = fma2(hv.x, wA0.x, acc[0][b]);
                acc[0][b] = fma2(hv.y, wB0.x, acc[0][b]);
                acc[1][b] = fma2(hv.x, wA0.y, acc[1][b]);
                acc[1][b] = fma2(hv.y, wB0.y, acc[1][b]);
                acc[2][b] = fma2(hv.x, wA1.x, acc[2][b]);
                acc[2][b] = fma2(hv.y, wB1.x, acc[2][b]);
                acc[3][b] = fma2(hv.x, wA1.y, acc[3][b]);
                acc[3][b] = fma2(hv.y, wB1.y, acc[3][b]);
            }
        }
        // ---- exchange: exch[((q*16 + b)*16 + h)*4 + ks] ----
        #pragma unroll
        for (int q = 0; q < 4; q++)
            #pragma unroll
            for (int b = 0; b < 4; b++) {
                float lo, hi; unpack2(acc[q][b], lo, hi);
                exch[((q*16 + bgrp*4 + b)*16 + hloc)*4 + ks] = lo + hi;
            }
        __syncthreads();

        // ---- pointwise for cell (pbg, phg) ----
        {
            float4 v0 = *(const float4*)&exch[((0*16+pb)*16+ph)*4];
            float4 v1 = *(const float4*)&exch[((1*16+pb)*16+ph)*4];
            float4 v2 = *(const float4*)&exch[((2*16+pb)*16+ph)*4];
            float4 v3 = *(const float4*)&exch[((3*16+pb)*16+ph)*4];
            float ai = xpi + (v0.x+v0.y) + (v0.z+v0.w);
            float af = xpf + (v1.x+v1.y) + (v1.z+v1.w);
            float ag = xpg + (v2.x+v2.y) + (v2.z+v2.w);
            float ao = xpo + (v3.x+v3.y) + (v3.z+v3.w);

            float ig = sigf(ai);
            float fg = sigf(af);
            float gg = __tanhf(ag);
            float og = sigf(ao);
            float cprev = c;
            float cy = fg*cprev + ig*gg;
            float hy = og*__tanhf(cy);
            c = cy;

            size_t oidx = (size_t)t*BH_ + (size_t)pbg*H_ + phg;
            out_h[oidx] = hy;
            g_hseq[(size_t)(t+1)*BH_ + (size_t)pbg*H_ + phg] = hy;
            g_f[oidx] = fg;
            float* dp = g_d + ((size_t)t*B_ + pbg)*H3_;
            dp[phg]        = gg*ig*(1.f-ig);
            dp[H_+phg]     = cprev*fg*(1.f-fg);
            dp[2*H_+phg]   = ig*(1.f-gg*gg);
            if (t == T_-1) out_cx[pbg*H_ + phg] = cy;
        }

        // ---- per-batch-group barrier (32 blocks) ----
        __threadfence();
        __syncthreads();
        if (bid != grpbase) {
            if (tid == 0) {
                strel32(&g_flags[bid], (unsigned)(t+1));
                while (ldacq32(&g_go4[bg]) < (unsigned)(t+1)) {}
            }
            __syncthreads();
        } else {
            if (tid >= 1 && tid < 32) {
                while (ldacq32(&g_flags[grpbase + tid]) < (unsigned)(t+1)) {}
            }
            __syncthreads();
            if (tid == 0) strel32(&g_go4[bg], (unsigned)(t+1));
        }
    }
}

// ---------------- K3: suffix forget-product scan (prefetch-4); ev_b -----------
__global__ void k3_suffix(float* __restrict__ out_evb)
{
    int idx = blockIdx.x*256 + threadIdx.x;   // < BH_
    int b = idx >> 9;
    int h = idx & 511;
    float p = 1.f, s0 = 0.f, s1 = 0.f, s2 = 0.f;

    float pdi[4], pdf[4], pdg[4], pfv[4];
    #pragma unroll
    for (int s = 0; s < 4; s++) {
        const float* dp = g_d + ((size_t)(T_-1-s)*B_ + b)*H3_;
        pdi[s] = dp[h]; pdf[s] = dp[H_+h]; pdg[s] = dp[2*H_+h];
        pfv[s] = g_f[(size_t)(T_-1-s)*BH_ + idx];
    }

    for (int tb = T_-1; tb >= 3; tb -= 4) {
        #pragma unroll
        for (int s = 0; s < 4; s++) {
            int t = tb - s;
            float cdi = pdi[s], cdf = pdf[s], cdg = pdg[s], cf = pfv[s];
            if (t >= 4) {
                const float* dn = g_d + ((size_t)(t-4)*B_ + b)*H3_;
                pdi[s] = dn[h]; pdf[s] = dn[H_+h]; pdg[s] = dn[2*H_+h];
                pfv[s] = g_f[(size_t)(t-4)*BH_ + idx];
            }
            float* dpc = g_d + ((size_t)t*B_ + b)*H3_;
            float wi = cdi*p, wf = cdf*p, wg = cdg*p;
            dpc[h] = wi; dpc[H_+h] = wf; dpc[2*H_+h] = wg;
            s0 += wi; s1 += wf; s2 += wg;
            p *= cf;
        }
    }
    out_evb[(size_t)b*H3_ + h]        = s0;
    out_evb[(size_t)b*H3_ + H_ + h]   = s1;
    out_evb[(size_t)b*H3_ + 2*H_ + h] = s2;
}

// ---------------- K4/K5: batched ev GEMM (f32x2, reg-DB) ----------------------
__global__ __launch_bounds__(256, 2) void k_ev(
    const float* __restrict__ Xin, float* __restrict__ C, int Idim)
{
    __shared__ __align__(16) float As[8][132];
    __shared__ __align__(16) float Xs[8][132];
    const float* X = Xin ? Xin : (const float*)g_hseq;
    int i0 = blockIdx.x*128;
    int j0 = blockIdx.y*128;
    int b  = blockIdx.z;
    int tid = threadIdx.x;
    int ty = tid/16, tx = tid%16;
    int lk = tid >> 5;
    int lj = (tid & 31) * 4;

    u64 acc2[8][4];
    #pragma unroll
    for (int i=0;i<8;i++)
        #pragma unroll
        for (int j=0;j<4;j++) acc2[i][j]=0ull;

    float4 rA, rX;
    {
        int t = lk;
        rA = *(const float4*)&g_d[((size_t)t*B_+b)*H3_ + j0 + lj];
        rX = *(const float4*)&X[((size_t)t*B_+b)*Idim + i0 + lj];
    }

    for (int t0 = 0; t0 < T_; t0 += 8) {
        *(float4*)&As[lk][lj] = rA;
        *(float4*)&Xs[lk][lj] = rX;
        __syncthreads();
        {
            int tn = t0 + 8 + lk;
            if (tn < T_) {
                rA = *(const float4*)&g_d[((size_t)tn*B_+b)*H3_ + j0 + lj];
                rX = *(const float4*)&X[((size_t)tn*B_+b)*Idim + i0 + lj];
            } else {
                rA = make_float4(0.f,0.f,0.f,0.f);
                rX = make_float4(0.f,0.f,0.f,0.f);
            }
        }
        #pragma unroll
        for (int kk=0;kk<8;kk++) {
            if (t0 + kk >= T_) break;
            float4 a0 = *(const float4*)&As[kk][ty*4];
            float4 a1 = *(const float4*)&As[kk][64+ty*4];
            ulonglong2 xv0 = *(const ulonglong2*)&Xs[kk][tx*4];
            ulonglong2 xv1 = *(const ulonglong2*)&Xs[kk][64+tx*4];
            u64 xx[4] = {xv0.x, xv0.y, xv1.x, xv1.y};
            float a[8] = {a0.x,a0.y,a0.z,a0.w,a1.x,a1.y,a1.z,a1.w};
            #pragma unroll
            for (int i=0;i<8;i++) {
                u64 ad = pack2(a[i], a[i]);
                #pragma unroll
                for (int j=0;j<4;j++) acc2[i][j] = fma2(ad, xx[j], acc2[i][j]);
            }
        }
        __syncthreads();
    }
    #pragma unroll
    for (int i=0;i<8;i++) {
        int j = j0 + ((i<4)? ty*4+i : 64+ty*4+(i-4));
        float* row = C + (size_t)b*H3_*Idim + (size_t)j*Idim + i0;
        float cr[8];
        unpack2(acc2[i][0], cr[0], cr[1]);
        unpack2(acc2[i][1], cr[2], cr[3]);
        unpack2(acc2[i][2], cr[4], cr[5]);
        unpack2(acc2[i][3], cr[6], cr[7]);
        *(float4*)&row[tx*4]    = make_float4(cr[0],cr[1],cr[2],cr[3]);
        *(float4*)&row[64+tx*4] = make_float4(cr[4],cr[5],cr[6],cr[7]);
    }
}

// ---------------- launch -------------------------------------------------------
extern "C" void kernel_launch(void* const* d_in, const int* in_sizes, int n_in,
                              void* d_out, int out_size)
{
    const float* input = (const float*)d_in[0];
    const float* h0    = (const float*)d_in[1];
    const float* c0    = (const float*)d_in[2];
    const float* Wih   = (const float*)d_in[3];
    const float* Whh   = (const float*)d_in[4];
    const float* bih   = (const float*)d_in[5];
    const float* bhh   = (const float*)d_in[6];

    float* out      = (float*)d_out;
    float* out_h    = out;
    float* out_cx   = out_h  + (size_t)T_*BH_;
    float* out_evih = out_cx + BH_;
    float* out_evhh = out_evih + (size_t)B_*H3_*I_;
    float* out_evb  = out_evhh + (size_t)B_*H3_*H_;

    const int dyn_smem = (256*WD2 + BB_*HS_STRIDE)*8 + 4096*4;  // ~184 KB
    cudaFuncSetAttribute(k_rec, cudaFuncAttributeMaxDynamicSharedMemorySize, dyn_smem);

    k_init<<<128,256>>>(h0);
    k1_xproj<<<dim3(16,50),256>>>(input, Wih, bih, bhh);
    k_rec<<<NBLK_, 256, dyn_smem>>>(Whh, c0, out_h, out_cx);
    k3_suffix<<<128,256>>>(out_evb);
    k_ev<<<dim3(I_/128, H3_/128, B_),256>>>(input, out_evih, I_);
    k_ev<<<dim3(H_/128, H3_/128, B_),256>>>(nullptr, out_evhh, H_);
}